// round 16
// baseline (speedup 1.0000x reference)
#include <cuda_runtime.h>
#include <cuda_fp16.h>
#include <cstdint>

#define BB 8
#define TT 2048
#define DD 256
#define BT (BB*TT)           // 16384
#define EPS_SUM 1e-8f
#define EPS_LN  1e-6f

// ---------------- scratch (device globals; no allocations allowed) ----------
__device__ __half g_vb1[BT*DD];
__device__ __half g_vb2[BT*DD];
__device__ __half g_ab1[BT*DD];
__device__ __half g_ab2[BT*DD];
__device__ __half g_S[(size_t)BB*TT*TT];   // 67 MB scores (fp16)
__device__ __half g_vout[BT*DD];           // half: feeds fc GEMM only
__device__ __half g_aout[BT*DD];
__device__ __half g_wv_h[DD*DD];           // preconverted Wvfc
__device__ __half g_wa_h[DD*DD];           // preconverted Wac
__device__ float  g_srow[BT];
__device__ float  g_scol[BT];

// ---------------- primitives -------------------------------------------------
__device__ __forceinline__ uint32_t sm_u32(const void* p) {
    return (uint32_t)__cvta_generic_to_shared(p);
}
__device__ __forceinline__ void ldsm4(uint32_t* r, uint32_t a) {
    asm volatile("ldmatrix.sync.aligned.m8n8.x4.shared.b16 {%0,%1,%2,%3},[%4];"
                 : "=r"(r[0]), "=r"(r[1]), "=r"(r[2]), "=r"(r[3]) : "r"(a));
}
__device__ __forceinline__ void ldsm4t(uint32_t* r, uint32_t a) {
    asm volatile("ldmatrix.sync.aligned.m8n8.x4.trans.shared.b16 {%0,%1,%2,%3},[%4];"
                 : "=r"(r[0]), "=r"(r[1]), "=r"(r[2]), "=r"(r[3]) : "r"(a));
}
__device__ __forceinline__ void mma16816(float* d, const uint32_t* a, const uint32_t* b) {
    asm volatile("mma.sync.aligned.m16n8k16.row.col.f32.f16.f16.f32 "
                 "{%0,%1,%2,%3},{%4,%5,%6,%7},{%8,%9},{%0,%1,%2,%3};"
                 : "+f"(d[0]), "+f"(d[1]), "+f"(d[2]), "+f"(d[3])
                 : "r"(a[0]), "r"(a[1]), "r"(a[2]), "r"(a[3]), "r"(b[0]), "r"(b[1]));
}
__device__ __forceinline__ void cpa16(uint32_t s, const void* g) {
    asm volatile("cp.async.cg.shared.global [%0],[%1],16;" :: "r"(s), "l"(g));
}
__device__ __forceinline__ void cpa_commit() { asm volatile("cp.async.commit_group;"); }
template<int N> __device__ __forceinline__ void cpa_wait() {
    asm volatile("cp.async.wait_group %0;" :: "n"(N));
}

#define LDA 40       // non-trans tiles (32-wide k) stride
#define LDT 136      // trans A tiles (128-wide m) stride
#define LDB2 264     // trans B tiles (256-wide n) stride

// Warp tile 32 x 64. ATR/BTR: 0 = non-trans ([x][LA]), 1 = trans ([k][LA/LB]).
template<int ATR, int BTR, int LA, int LB>
__device__ __forceinline__ void warp_mma(const __half* As, const __half* Bs,
                                         float (&acc)[2][8][4], int lane, int wm, int wn, int kk) {
    uint32_t af[2][4], bf[4][4];
#pragma unroll
    for (int i = 0; i < 2; i++) {
        int mb = wm + i * 16;
        if (ATR == 0) {
            uint32_t addr = sm_u32(As + (mb + (lane & 15)) * LA + kk + (lane >> 4) * 8);
            ldsm4(af[i], addr);
        } else {
            uint32_t addr = sm_u32(As + (kk + (lane & 7) + ((lane >> 4) & 1) * 8) * LA
                                      + mb + ((lane >> 3) & 1) * 8);
            ldsm4t(af[i], addr);
        }
    }
#pragma unroll
    for (int jj = 0; jj < 4; jj++) {
        int nb = wn + jj * 16;
        if (BTR == 0) {
            uint32_t addr = sm_u32(Bs + (nb + (lane & 7) + ((lane >> 4) ? 8 : 0)) * LB
                                      + kk + ((lane >> 3) & 1) * 8);
            ldsm4(bf[jj], addr);
        } else {
            uint32_t addr = sm_u32(Bs + (kk + (lane & 7) + ((lane >> 3) & 1) * 8) * LB
                                      + nb + ((lane >> 4) ? 8 : 0));
            ldsm4t(bf[jj], addr);
        }
    }
#pragma unroll
    for (int i = 0; i < 2; i++)
#pragma unroll
        for (int jj = 0; jj < 4; jj++) {
            mma16816(acc[i][2*jj],     af[i], &bf[jj][0]);
            mma16816(acc[i][2*jj + 1], af[i], &bf[jj][2]);
        }
}

// ---------------- K1: four input GEMMs relu(X @ W^T) -> half -----------------
// z==0 blocks zero g_srow/g_scol; z==1 blocks preconvert Wvfc/Wac to half.
__global__ __launch_bounds__(256) void k_in_gemm(const float* __restrict__ v_f,
                                                 const float* __restrict__ a_f,
                                                 const float* __restrict__ Wv1,
                                                 const float* __restrict__ Wv2,
                                                 const float* __restrict__ Wa1,
                                                 const float* __restrict__ Wa2,
                                                 const float* __restrict__ Wvfc,
                                                 const float* __restrict__ Wac) {
    __shared__ __half As[128 * LDA];
    __shared__ __half Bs[128 * LDA];
    int z = blockIdx.z;
    int t = threadIdx.x;
    int id = (blockIdx.y * 2 + blockIdx.x) * 256 + t;
    if (z == 0) {
        if (id < BT) { g_srow[id] = 0.f; g_scol[id] = 0.f; }
    } else if (z == 1) {
        g_wv_h[id] = __float2half_rn(Wvfc[id]);
        g_wa_h[id] = __float2half_rn(Wac[id]);
    }
    const float* X = (z < 2) ? v_f : a_f;
    const float* W = (z == 0) ? Wv1 : (z == 1) ? Wv2 : (z == 2) ? Wa1 : Wa2;
    __half* C = (z == 0) ? g_vb1 : (z == 1) ? g_vb2 : (z == 2) ? g_ab1 : g_ab2;
    int m0 = blockIdx.y * 128, n0 = blockIdx.x * 128;
    int lane = t & 31, w = t >> 5;
    int wm = (w & 3) * 32, wn = (w >> 2) * 64;
    float acc[2][8][4] = {};

    for (int k0 = 0; k0 < DD; k0 += 32) {
#pragma unroll
        for (int it = 0; it < 4; it++) {
            int m = it * 32 + (t >> 3);
            int k4 = (t & 7) * 4;
            float4 xa = *(const float4*)&X[(m0 + m) * DD + k0 + k4];
            float4 wb = *(const float4*)&W[(n0 + m) * DD + k0 + k4];
            *(__half2*)&As[m * LDA + k4]     = __floats2half2_rn(xa.x, xa.y);
            *(__half2*)&As[m * LDA + k4 + 2] = __floats2half2_rn(xa.z, xa.w);
            *(__half2*)&Bs[m * LDA + k4]     = __floats2half2_rn(wb.x, wb.y);
            *(__half2*)&Bs[m * LDA + k4 + 2] = __floats2half2_rn(wb.z, wb.w);
        }
        __syncthreads();
        warp_mma<0,0,LDA,LDA>(As, Bs, acc, lane, wm, wn, 0);
        warp_mma<0,0,LDA,LDA>(As, Bs, acc, lane, wm, wn, 16);
        __syncthreads();
    }
#pragma unroll
    for (int i = 0; i < 2; i++) {
        int r = m0 + wm + i * 16 + (lane >> 2);
#pragma unroll
        for (int j = 0; j < 8; j++) {
            int c = n0 + wn + j * 8 + 2 * (lane & 3);
            float* d = acc[i][j];
            *(__half2*)&C[(size_t)r * DD + c] =
                __floats2half2_rn(fmaxf(d[0], 0.f), fmaxf(d[1], 0.f));
            *(__half2*)&C[(size_t)(r + 8) * DD + c] =
                __floats2half2_rn(fmaxf(d[2], 0.f), fmaxf(d[3], 0.f));
        }
    }
}

// ---------------- K2: S = relu(Vb2 @ Ab1^T / 16) -> half, + row/col sums -----
// Register-staged double-buffered pipeline (proven R8 config).
__global__ __launch_bounds__(256) void k_scores() {
    __shared__ __half As[2][128 * LDA];
    __shared__ __half Bs[2][128 * LDA];
    __shared__ float srow_s[128];
    __shared__ float scol_s[128];
    int b = blockIdx.z;
    const __half* A  = g_vb2 + (size_t)b * TT * DD;
    const __half* Bm = g_ab1 + (size_t)b * TT * DD;
    __half* C = g_S + (size_t)b * TT * TT;
    int m0 = blockIdx.y * 128, n0 = blockIdx.x * 128;
    int t = threadIdx.x, lane = t & 31, w = t >> 5;
    int wm = (w & 3) * 32, wn = (w >> 2) * 64;
    if (t < 128) { srow_s[t] = 0.f; scol_s[t] = 0.f; }
    int mld = t >> 3, k4 = (t & 7) * 4;
    float acc[2][8][4] = {};
    uint2 ra[4], rb[4];

#pragma unroll
    for (int it = 0; it < 4; it++) {
        int m = it * 32 + mld;
        ra[it] = *(const uint2*)&A[(size_t)(m0 + m) * DD + k4];
        rb[it] = *(const uint2*)&Bm[(size_t)(n0 + m) * DD + k4];
    }
#pragma unroll
    for (int it = 0; it < 4; it++) {
        int m = it * 32 + mld;
        *(uint2*)&As[0][m * LDA + k4] = ra[it];
        *(uint2*)&Bs[0][m * LDA + k4] = rb[it];
    }
    __syncthreads();

    for (int kt = 0; kt < 8; kt++) {
        int cur = kt & 1;
        if (kt < 7) {
            int k0 = (kt + 1) * 32;
#pragma unroll
            for (int it = 0; it < 4; it++) {
                int m = it * 32 + mld;
                ra[it] = *(const uint2*)&A[(size_t)(m0 + m) * DD + k0 + k4];
                rb[it] = *(const uint2*)&Bm[(size_t)(n0 + m) * DD + k0 + k4];
            }
        }
        warp_mma<0,0,LDA,LDA>(As[cur], Bs[cur], acc, lane, wm, wn, 0);
        warp_mma<0,0,LDA,LDA>(As[cur], Bs[cur], acc, lane, wm, wn, 16);
        if (kt < 7) {
#pragma unroll
            for (int it = 0; it < 4; it++) {
                int m = it * 32 + mld;
                *(uint2*)&As[cur ^ 1][m * LDA + k4] = ra[it];
                *(uint2*)&Bs[cur ^ 1][m * LDA + k4] = rb[it];
            }
        }
        __syncthreads();
    }

#pragma unroll
    for (int i = 0; i < 2; i++) {
        int rl = wm + i * 16 + (lane >> 2);
#pragma unroll
        for (int j = 0; j < 8; j++) {
            int cl = wn + j * 8 + 2 * (lane & 3);
            float* d = acc[i][j];
            float v0 = fmaxf(d[0] * 0.0625f, 0.f);
            float v1 = fmaxf(d[1] * 0.0625f, 0.f);
            float v2 = fmaxf(d[2] * 0.0625f, 0.f);
            float v3 = fmaxf(d[3] * 0.0625f, 0.f);
            *(__half2*)&C[(size_t)(m0 + rl) * TT + n0 + cl]     = __floats2half2_rn(v0, v1);
            *(__half2*)&C[(size_t)(m0 + rl + 8) * TT + n0 + cl] = __floats2half2_rn(v2, v3);
            atomicAdd(&srow_s[rl],     v0 + v1);
            atomicAdd(&srow_s[rl + 8], v2 + v3);
            atomicAdd(&scol_s[cl],     v0 + v2);
            atomicAdd(&scol_s[cl + 1], v1 + v3);
        }
    }
    __syncthreads();
    if (t < 128) {
        atomicAdd(&g_srow[b * TT + m0 + t], srow_s[t]);
        atomicAdd(&g_scol[b * TT + n0 + t], scol_s[t]);
    }
}

// mask 8 halfs (uint4) against threshold tr (fp32 compare), accumulate into accm
__device__ __forceinline__ uint4 mask8(uint4 x, float tr, float& accm) {
    __half2* h = (__half2*)&x;
    uint4 r;
    __half2* o = (__half2*)&r;
#pragma unroll
    for (int i = 0; i < 4; i++) {
        float2 f = __half22float2(h[i]);
        float a0 = f.x > tr ? f.x : 0.f;
        float a1 = f.y > tr ? f.y : 0.f;
        accm += a0 + a1;
        o[i] = __floats2half2_rn(a0, a1);
    }
    return r;
}

// SMEM sizing for the merged agg kernel: A double-buffered (register-staged),
// B 3-stage cp.async.
#define AGGV_AS   (128 * LDA)                 // 5120 halfs per buffer
#define AGGV_BS   (32 * LDB2)                 // 8448 halfs per buffer
#define AGGA_AS   (32 * LDT)                  // 4352 halfs per buffer
#define AGG_SMEM  ((2*AGGV_AS + 3*AGGV_BS) * 2 + 3 * 128 * 4)   // v-role is larger

// ---------------- v-role body: v_out = v_f + (masked S) @ Ab2 * rcp_row ------
__device__ __forceinline__ void agg_v_body(char* smraw, const float* __restrict__ v_f,
                                           const float* __restrict__ thr_p) {
    __half* As   = (__half*)smraw;                        // [2][128*LDA]
    __half* Bst  = As + 2 * AGGV_AS;                      // [3][32*LDB2]
    float*  trs  = (float*)(Bst + 3 * AGGV_BS);           // [128]
    float*  ses  = trs + 128;
    float*  msum = ses + 128;
    int b = blockIdx.y, m0 = blockIdx.x * 128;
    int t = threadIdx.x, lane = t & 31, w = t >> 5;
    int wm = (w & 3) * 32, wn = (w >> 2) * 64;
    if (t < 128) {
        float s = g_srow[b * TT + m0 + t] + EPS_SUM;
        ses[t] = s;
        trs[t] = thr_p[0] * s;
        msum[t] = 0.f;
    }
    const __half* Sb = g_S + (size_t)b * TT * TT;
    const __half* Bg = g_ab2 + (size_t)b * TT * DD;
    float acc[2][8][4] = {};
    float macc = 0.f;
    int srow0 = t >> 2, sseg = (t & 3) * 8;
    int bq = t >> 5, bn8 = (t & 31) * 8;
    uint4 xs;

    auto issueB = [&](int st, int k0) {
        uint32_t b0 = sm_u32(Bst + st * AGGV_BS);
        cpa16(b0 + (bq * LDB2 + bn8) * 2,        &Bg[(size_t)(k0 + bq) * DD + bn8]);
        cpa16(b0 + ((bq + 16) * LDB2 + bn8) * 2, &Bg[(size_t)(k0 + bq + 16) * DD + bn8]);
        cpa_commit();
    };
    issueB(0, 0);
    issueB(1, 32);
    __syncthreads();   // trs ready before mask8
    xs = *(const uint4*)&Sb[(size_t)(m0 + srow0) * TT + sseg];
    *(uint4*)&As[srow0 * LDA + sseg] = mask8(xs, trs[srow0], macc);

    for (int kt = 0; kt < 64; kt++) {
        if (kt == 63) cpa_wait<0>(); else cpa_wait<1>();
        __syncthreads();
        int cur = kt & 1;
        if (kt < 63) {
            int k0 = (kt + 1) * 32;
            xs = *(const uint4*)&Sb[(size_t)(m0 + srow0) * TT + k0 + sseg];
        }
        const __half* Ac = As + cur * AGGV_AS;
        const __half* Bc = Bst + (kt % 3) * AGGV_BS;
        warp_mma<0,1,LDA,LDB2>(Ac, Bc, acc, lane, wm, wn, 0);
        warp_mma<0,1,LDA,LDB2>(Ac, Bc, acc, lane, wm, wn, 16);
        if (kt < 63) {
            __half* An = As + (cur ^ 1) * AGGV_AS;
            *(uint4*)&An[srow0 * LDA + sseg] = mask8(xs, trs[srow0], macc);
            issueB((kt + 2) % 3, (kt + 2) * 32);
        }
    }
    __syncthreads();
    atomicAdd(&msum[srow0], macc);
    __syncthreads();
#pragma unroll
    for (int i = 0; i < 2; i++) {
        int rl = wm + i * 16 + (lane >> 2);
        int row0 = b * TT + m0 + rl;
        int row8 = row0 + 8;
        float rcp0 = 1.f / (msum[rl]     + EPS_SUM * ses[rl]);
        float rcp8 = 1.f / (msum[rl + 8] + EPS_SUM * ses[rl + 8]);
#pragma unroll
        for (int j = 0; j < 8; j++) {
            int c = wn + j * 8 + 2 * (lane & 3);
            float* d = acc[i][j];
            size_t o0 = (size_t)row0 * DD + c;
            size_t o8 = (size_t)row8 * DD + c;
            *(__half2*)&g_vout[o0] =
                __floats2half2_rn(v_f[o0] + d[0] * rcp0, v_f[o0 + 1] + d[1] * rcp0);
            *(__half2*)&g_vout[o8] =
                __floats2half2_rn(v_f[o8] + d[2] * rcp8, v_f[o8 + 1] + d[3] * rcp8);
        }
    }
}

// ---------------- a-role body: a_out = a_f + (masked S)^T @ Vb1 * rcp_col ----
__device__ __forceinline__ void agg_a_body(char* smraw, const float* __restrict__ a_f,
                                           const float* __restrict__ thr_p) {
    __half* Ast  = (__half*)smraw;                        // [2][32*LDT]
    __half* Bst  = Ast + 2 * AGGA_AS;                     // [3][32*LDB2]
    float*  tcs  = (float*)(Bst + 3 * AGGV_BS);           // [128]
    float*  ces  = tcs + 128;
    float*  msum = ces + 128;
    int b = blockIdx.y, m0 = blockIdx.x * 128;
    int t = threadIdx.x, lane = t & 31, w = t >> 5;
    int wm = (w & 3) * 32, wn = (w >> 2) * 64;
    if (t < 128) {
        float s = g_scol[b * TT + m0 + t] + EPS_SUM;
        ces[t] = s;
        tcs[t] = thr_p[0] * s;
        msum[t] = 0.f;
    }
    const __half* Sb = g_S + (size_t)b * TT * TT;
    const __half* Bg = g_vb1 + (size_t)b * TT * DD;
    float acc[2][8][4] = {};
    float cacc[8] = {};
    int sk0 = t >> 4, m8 = (t & 15) * 8;
    int bq = t >> 5, bn8 = (t & 31) * 8;
    uint4 xs;

    auto maskc = [&](uint4 x) {
        __half2* h = (__half2*)&x;
        uint4 r;
        __half2* o = (__half2*)&r;
#pragma unroll
        for (int i = 0; i < 4; i++) {
            float2 f = __half22float2(h[i]);
            float a0 = f.x > tcs[m8 + 2*i]     ? f.x : 0.f;
            float a1 = f.y > tcs[m8 + 2*i + 1] ? f.y : 0.f;
            cacc[2*i]     += a0;
            cacc[2*i + 1] += a1;
            o[i] = __floats2half2_rn(a0, a1);
        }
        return r;
    };

    auto issueB = [&](int st, int k0) {
        uint32_t b0 = sm_u32(Bst + st * AGGV_BS);
        cpa16(b0 + (bq * LDB2 + bn8) * 2,        &Bg[(size_t)(k0 + bq) * DD + bn8]);
        cpa16(b0 + ((bq + 16) * LDB2 + bn8) * 2, &Bg[(size_t)(k0 + bq + 16) * DD + bn8]);
        cpa_commit();
    };
    issueB(0, 0);
    issueB(1, 32);
    __syncthreads();   // tcs ready before maskc
    xs = *(const uint4*)&Sb[(size_t)sk0 * TT + m0 + m8];
    *(uint4*)&Ast[sk0 * LDT + m8] = maskc(xs);

    for (int kt = 0; kt < 64; kt++) {
        if (kt == 63) cpa_wait<0>(); else cpa_wait<1>();
        __syncthreads();
        int cur = kt & 1;
        if (kt < 63) {
            int k0 = (kt + 1) * 32;
            xs = *(const uint4*)&Sb[(size_t)(k0 + sk0) * TT + m0 + m8];
        }
        const __half* Ac = Ast + cur * AGGA_AS;
        const __half* Bc = Bst + (kt % 3) * AGGV_BS;
        warp_mma<1,1,LDT,LDB2>(Ac, Bc, acc, lane, wm, wn, 0);
        warp_mma<1,1,LDT,LDB2>(Ac, Bc, acc, lane, wm, wn, 16);
        if (kt < 63) {
            __half* An = Ast + (cur ^ 1) * AGGA_AS;
            *(uint4*)&An[sk0 * LDT + m8] = maskc(xs);
            issueB((kt + 2) % 3, (kt + 2) * 32);
        }
    }
    __syncthreads();
#pragma unroll
    for (int q = 0; q < 8; q++)
        atomicAdd(&msum[m8 + q], cacc[q]);
    __syncthreads();
#pragma unroll
    for (int i = 0; i < 2; i++) {
        int rl = wm + i * 16 + (lane >> 2);
        int row0 = b * TT + m0 + rl;
        int row8 = row0 + 8;
        float rcp0 = 1.f / (msum[rl]     + EPS_SUM * ces[rl]);
        float rcp8 = 1.f / (msum[rl + 8] + EPS_SUM * ces[rl + 8]);
#pragma unroll
        for (int j = 0; j < 8; j++) {
            int c = wn + j * 8 + 2 * (lane & 3);
            float* d = acc[i][j];
            size_t o0 = (size_t)row0 * DD + c;
            size_t o8 = (size_t)row8 * DD + c;
            *(__half2*)&g_aout[o0] =
                __floats2half2_rn(a_f[o0] + d[0] * rcp0, a_f[o0 + 1] + d[1] * rcp0);
            *(__half2*)&g_aout[o8] =
                __floats2half2_rn(a_f[o8] + d[2] * rcp8, a_f[o8 + 1] + d[3] * rcp8);
        }
    }
}

// ---------------- merged agg kernel: z=0 -> v role, z=1 -> a role ------------
__global__ __launch_bounds__(512, 1) void k_agg(const float* __restrict__ v_f,
                                                const float* __restrict__ a_f,
                                                const float* __restrict__ thr_p) {
    extern __shared__ char smraw[];
    if (blockIdx.z == 0) agg_v_body(smraw, v_f, thr_p);
    else                 agg_a_body(smraw, a_f, thr_p);
}

// ---------------- K6: fused output GEMMs + relu + layernorm + combine --------
// 3-stage cp.async pipeline; NO SMEM park tile: z=1 reads back the vp values
// this same thread wrote to `out` in z=0 (per-thread program order guarantees
// the load sees the store; the 64KB tile is L1/L2-resident).
#define OUT_AB (64 * LDA)
#define OUT_BB (256 * LDA)
#define OUT_SMEM (3*OUT_AB*2 + 3*OUT_BB*2 + (64 + 64 + 256 + 256)*4)
__global__ __launch_bounds__(256) void k_out_ln(const float* __restrict__ lns,
                                                const float* __restrict__ lnb,
                                                float* __restrict__ out) {
    extern __shared__ char smraw[];
    __half* As  = (__half*)smraw;                  // [3][64*LDA]
    __half* Bs  = As + 3 * OUT_AB;                 // [3][256*LDA]
    float* rsum = (float*)(Bs + 3 * OUT_BB);       // 64
    float* rsq  = rsum + 64;                       // 64
    float* scs  = rsq + 64;                        // 256
    float* bis  = scs + 256;                       // 256
    int m0 = blockIdx.x * 64;
    int t = threadIdx.x, lane = t & 31, w = t >> 5;
    int wm = (w & 1) * 32, wn = (w >> 1) * 64;
    scs[t] = lns[t];
    bis[t] = lnb[t];
    int ar = t >> 2, sg = (t & 3) * 8;   // A: 1 chunk/thread; B: 4 chunks/thread
    const float* vp = out + (size_t)BT * DD;       // v_out block of the output

    for (int z = 0; z < 2; z++) {
        const __half* X = z ? g_aout : g_vout;
        const __half* Wh = z ? g_wa_h : g_wv_h;
        float acc[2][8][4] = {};

        auto issue = [&](int st, int k0) {
            uint32_t a0 = sm_u32(As + st * OUT_AB);
            uint32_t b0 = sm_u32(Bs + st * OUT_BB);
            cpa16(a0 + (ar * LDA + sg) * 2, &X[(size_t)(m0 + ar) * DD + k0 + sg]);
#pragma unroll
            for (int q = 0; q < 4; q++) {
                int n = q * 64 + ar;
                cpa16(b0 + (n * LDA + sg) * 2, &Wh[(size_t)n * DD + k0 + sg]);
            }
            cpa_commit();
        };
        issue(0, 0);
        issue(1, 32);

        for (int kt = 0; kt < 8; kt++) {
            if (kt == 7) cpa_wait<0>(); else cpa_wait<1>();
            __syncthreads();
            int cur = kt % 3;
            warp_mma<0,0,LDA,LDA>(As + cur * OUT_AB, Bs + cur * OUT_BB, acc, lane, wm, wn, 0);
            warp_mma<0,0,LDA,LDA>(As + cur * OUT_AB, Bs + cur * OUT_BB, acc, lane, wm, wn, 16);
            if (kt + 2 < 8) issue((kt + 2) % 3, (kt + 2) * 32);
            __syncthreads();
        }

        // relu + per-row sum/sumsq partials
        if (t < 64) { rsum[t] = 0.f; rsq[t] = 0.f; }
        __syncthreads();
#pragma unroll
        for (int i = 0; i < 2; i++) {
            float ps0 = 0.f, pq0 = 0.f, ps1 = 0.f, pq1 = 0.f;
#pragma unroll
            for (int j = 0; j < 8; j++) {
                float* d = acc[i][j];
                d[0] = fmaxf(d[0], 0.f); d[1] = fmaxf(d[1], 0.f);
                d[2] = fmaxf(d[2], 0.f); d[3] = fmaxf(d[3], 0.f);
                ps0 += d[0] + d[1]; pq0 += d[0]*d[0] + d[1]*d[1];
                ps1 += d[2] + d[3]; pq1 += d[2]*d[2] + d[3]*d[3];
            }
            int rl = wm + i * 16 + (lane >> 2);
            atomicAdd(&rsum[rl], ps0);     atomicAdd(&rsq[rl], pq0);
            atomicAdd(&rsum[rl + 8], ps1); atomicAdd(&rsq[rl + 8], pq1);
        }
        __syncthreads();

        // layernorm; z=0 writes vp, z=1 writes ap and av (reading vp back)
        float* dst = out + (size_t)(z + 1) * BT * DD;
#pragma unroll
        for (int i = 0; i < 2; i++) {
#pragma unroll
            for (int h = 0; h < 2; h++) {
                int rl = wm + i * 16 + (lane >> 2) + h * 8;
                float mu = rsum[rl] * (1.f / 256.f);
                float var = rsq[rl] * (1.f / 256.f) - mu * mu;
                float rr = rsqrtf(var + EPS_LN);
                size_t rowoff = (size_t)(m0 + rl) * DD;
#pragma unroll
                for (int j = 0; j < 8; j++) {
                    int c = wn + j * 8 + 2 * (lane & 3);
                    float* d = acc[i][j];
                    float o0 = (d[h*2]     - mu) * rr * scs[c]     + bis[c];
                    float o1 = (d[h*2 + 1] - mu) * rr * scs[c + 1] + bis[c + 1];
                    *(float2*)&dst[rowoff + c] = make_float2(o0, o1);
                    if (z == 1) {
                        float2 vv = *(const float2*)&vp[rowoff + c];
                        *(float2*)&out[rowoff + c] =
                            make_float2(0.4f * (o0 + vv.x), 0.4f * (o1 + vv.y));
                    }
                }
            }
        }
        __syncthreads();
    }
}

// ---------------- launch -----------------------------------------------------
extern "C" void kernel_launch(void* const* d_in, const int* in_sizes, int n_in,
                              void* d_out, int out_size) {
    const float* a_f  = (const float*)d_in[0];
    const float* v_f  = (const float*)d_in[1];
    const float* thr  = (const float*)d_in[2];
    const float* Wv1  = (const float*)d_in[3];
    const float* Wv2  = (const float*)d_in[4];
    const float* Wvfc = (const float*)d_in[5];
    const float* Wa1  = (const float*)d_in[6];
    const float* Wa2  = (const float*)d_in[7];
    const float* Wac  = (const float*)d_in[8];
    const float* lns  = (const float*)d_in[9];
    const float* lnb  = (const float*)d_in[10];
    float* out = (float*)d_out;

    cudaFuncSetAttribute(k_agg, cudaFuncAttributeMaxDynamicSharedMemorySize, AGG_SMEM);
    cudaFuncSetAttribute(k_out_ln, cudaFuncAttributeMaxDynamicSharedMemorySize, OUT_SMEM);

    k_in_gemm<<<dim3(2, 128, 4), 256>>>(v_f, a_f, Wv1, Wv2, Wa1, Wa2, Wvfc, Wac);
    k_scores<<<dim3(16, 16, 8), 256>>>();
    k_agg<<<dim3(16, 8, 2), 512, AGG_SMEM>>>(v_f, a_f, thr);
    k_out_ln<<<BT/64, 256, OUT_SMEM>>>(lns, lnb, out);
}

// round 17
// speedup vs baseline: 1.8369x; 1.8369x over previous
#include <cuda_runtime.h>
#include <cuda_fp16.h>
#include <cstdint>

#define BB 8
#define TT 2048
#define DD 256
#define BT (BB*TT)           // 16384
#define EPS_SUM 1e-8f
#define EPS_LN  1e-6f

// ---------------- scratch (device globals; no allocations allowed) ----------
__device__ __half g_vb1[BT*DD];
__device__ __half g_vb2[BT*DD];
__device__ __half g_ab1[BT*DD];
__device__ __half g_ab2[BT*DD];
__device__ __half g_S[(size_t)BB*TT*TT];   // 67 MB scores (fp16)
__device__ __half g_vout[BT*DD];           // half: feeds fc GEMM only
__device__ __half g_aout[BT*DD];
__device__ __half g_wv_h[DD*DD];           // preconverted Wvfc
__device__ __half g_wa_h[DD*DD];           // preconverted Wac
__device__ float  g_srow[BT];
__device__ float  g_scol[BT];

// ---------------- primitives -------------------------------------------------
__device__ __forceinline__ uint32_t sm_u32(const void* p) {
    return (uint32_t)__cvta_generic_to_shared(p);
}
__device__ __forceinline__ void ldsm4(uint32_t* r, uint32_t a) {
    asm volatile("ldmatrix.sync.aligned.m8n8.x4.shared.b16 {%0,%1,%2,%3},[%4];"
                 : "=r"(r[0]), "=r"(r[1]), "=r"(r[2]), "=r"(r[3]) : "r"(a));
}
__device__ __forceinline__ void ldsm4t(uint32_t* r, uint32_t a) {
    asm volatile("ldmatrix.sync.aligned.m8n8.x4.trans.shared.b16 {%0,%1,%2,%3},[%4];"
                 : "=r"(r[0]), "=r"(r[1]), "=r"(r[2]), "=r"(r[3]) : "r"(a));
}
__device__ __forceinline__ void mma16816(float* d, const uint32_t* a, const uint32_t* b) {
    asm volatile("mma.sync.aligned.m16n8k16.row.col.f32.f16.f16.f32 "
                 "{%0,%1,%2,%3},{%4,%5,%6,%7},{%8,%9},{%0,%1,%2,%3};"
                 : "+f"(d[0]), "+f"(d[1]), "+f"(d[2]), "+f"(d[3])
                 : "r"(a[0]), "r"(a[1]), "r"(a[2]), "r"(a[3]), "r"(b[0]), "r"(b[1]));
}
__device__ __forceinline__ void cpa16(uint32_t s, const void* g) {
    asm volatile("cp.async.cg.shared.global [%0],[%1],16;" :: "r"(s), "l"(g));
}
__device__ __forceinline__ void cpa_commit() { asm volatile("cp.async.commit_group;"); }
template<int N> __device__ __forceinline__ void cpa_wait() {
    asm volatile("cp.async.wait_group %0;" :: "n"(N));
}

#define LDA 40       // non-trans tiles (32-wide k) stride
#define LDT 136      // trans A tiles (128-wide m) stride
#define LDB2 264     // trans B tiles (256-wide n) stride

// Warp tile 32 x 64. ATR/BTR: 0 = non-trans ([x][LA]), 1 = trans ([k][LA/LB]).
template<int ATR, int BTR, int LA, int LB>
__device__ __forceinline__ void warp_mma(const __half* As, const __half* Bs,
                                         float (&acc)[2][8][4], int lane, int wm, int wn, int kk) {
    uint32_t af[2][4], bf[4][4];
#pragma unroll
    for (int i = 0; i < 2; i++) {
        int mb = wm + i * 16;
        if (ATR == 0) {
            uint32_t addr = sm_u32(As + (mb + (lane & 15)) * LA + kk + (lane >> 4) * 8);
            ldsm4(af[i], addr);
        } else {
            uint32_t addr = sm_u32(As + (kk + (lane & 7) + ((lane >> 4) & 1) * 8) * LA
                                      + mb + ((lane >> 3) & 1) * 8);
            ldsm4t(af[i], addr);
        }
    }
#pragma unroll
    for (int jj = 0; jj < 4; jj++) {
        int nb = wn + jj * 16;
        if (BTR == 0) {
            uint32_t addr = sm_u32(Bs + (nb + (lane & 7) + ((lane >> 4) ? 8 : 0)) * LB
                                      + kk + ((lane >> 3) & 1) * 8);
            ldsm4(bf[jj], addr);
        } else {
            uint32_t addr = sm_u32(Bs + (kk + (lane & 7) + ((lane >> 3) & 1) * 8) * LB
                                      + nb + ((lane >> 4) ? 8 : 0));
            ldsm4t(bf[jj], addr);
        }
    }
#pragma unroll
    for (int i = 0; i < 2; i++)
#pragma unroll
        for (int jj = 0; jj < 4; jj++) {
            mma16816(acc[i][2*jj],     af[i], &bf[jj][0]);
            mma16816(acc[i][2*jj + 1], af[i], &bf[jj][2]);
        }
}

// ---------------- K1: four input GEMMs relu(X @ W^T) -> half -----------------
// z==0 blocks zero g_srow/g_scol; z==1 blocks preconvert Wvfc/Wac to half.
__global__ __launch_bounds__(256) void k_in_gemm(const float* __restrict__ v_f,
                                                 const float* __restrict__ a_f,
                                                 const float* __restrict__ Wv1,
                                                 const float* __restrict__ Wv2,
                                                 const float* __restrict__ Wa1,
                                                 const float* __restrict__ Wa2,
                                                 const float* __restrict__ Wvfc,
                                                 const float* __restrict__ Wac) {
    __shared__ __half As[128 * LDA];
    __shared__ __half Bs[128 * LDA];
    int z = blockIdx.z;
    int t = threadIdx.x;
    int id = (blockIdx.y * 2 + blockIdx.x) * 256 + t;
    if (z == 0) {
        if (id < BT) { g_srow[id] = 0.f; g_scol[id] = 0.f; }
    } else if (z == 1) {
        g_wv_h[id] = __float2half_rn(Wvfc[id]);
        g_wa_h[id] = __float2half_rn(Wac[id]);
    }
    const float* X = (z < 2) ? v_f : a_f;
    const float* W = (z == 0) ? Wv1 : (z == 1) ? Wv2 : (z == 2) ? Wa1 : Wa2;
    __half* C = (z == 0) ? g_vb1 : (z == 1) ? g_vb2 : (z == 2) ? g_ab1 : g_ab2;
    int m0 = blockIdx.y * 128, n0 = blockIdx.x * 128;
    int lane = t & 31, w = t >> 5;
    int wm = (w & 3) * 32, wn = (w >> 2) * 64;
    float acc[2][8][4] = {};

    for (int k0 = 0; k0 < DD; k0 += 32) {
#pragma unroll
        for (int it = 0; it < 4; it++) {
            int m = it * 32 + (t >> 3);
            int k4 = (t & 7) * 4;
            float4 xa = *(const float4*)&X[(m0 + m) * DD + k0 + k4];
            float4 wb = *(const float4*)&W[(n0 + m) * DD + k0 + k4];
            *(__half2*)&As[m * LDA + k4]     = __floats2half2_rn(xa.x, xa.y);
            *(__half2*)&As[m * LDA + k4 + 2] = __floats2half2_rn(xa.z, xa.w);
            *(__half2*)&Bs[m * LDA + k4]     = __floats2half2_rn(wb.x, wb.y);
            *(__half2*)&Bs[m * LDA + k4 + 2] = __floats2half2_rn(wb.z, wb.w);
        }
        __syncthreads();
        warp_mma<0,0,LDA,LDA>(As, Bs, acc, lane, wm, wn, 0);
        warp_mma<0,0,LDA,LDA>(As, Bs, acc, lane, wm, wn, 16);
        __syncthreads();
    }
#pragma unroll
    for (int i = 0; i < 2; i++) {
        int r = m0 + wm + i * 16 + (lane >> 2);
#pragma unroll
        for (int j = 0; j < 8; j++) {
            int c = n0 + wn + j * 8 + 2 * (lane & 3);
            float* d = acc[i][j];
            *(__half2*)&C[(size_t)r * DD + c] =
                __floats2half2_rn(fmaxf(d[0], 0.f), fmaxf(d[1], 0.f));
            *(__half2*)&C[(size_t)(r + 8) * DD + c] =
                __floats2half2_rn(fmaxf(d[2], 0.f), fmaxf(d[3], 0.f));
        }
    }
}

// ---------------- K2: S = relu(Vb2 @ Ab1^T / 16) -> half, + row/col sums -----
// Register-staged double-buffered pipeline; epilogue sums register-accumulated
// (srow: 4 atomics/thread, scol: 16 atomics/thread instead of 64 total).
__global__ __launch_bounds__(256) void k_scores() {
    __shared__ __half As[2][128 * LDA];
    __shared__ __half Bs[2][128 * LDA];
    __shared__ float srow_s[128];
    __shared__ float scol_s[128];
    int b = blockIdx.z;
    const __half* A  = g_vb2 + (size_t)b * TT * DD;
    const __half* Bm = g_ab1 + (size_t)b * TT * DD;
    __half* C = g_S + (size_t)b * TT * TT;
    int m0 = blockIdx.y * 128, n0 = blockIdx.x * 128;
    int t = threadIdx.x, lane = t & 31, w = t >> 5;
    int wm = (w & 3) * 32, wn = (w >> 2) * 64;
    if (t < 128) { srow_s[t] = 0.f; scol_s[t] = 0.f; }
    int mld = t >> 3, k4 = (t & 7) * 4;
    float acc[2][8][4] = {};
    uint2 ra[4], rb[4];

#pragma unroll
    for (int it = 0; it < 4; it++) {
        int m = it * 32 + mld;
        ra[it] = *(const uint2*)&A[(size_t)(m0 + m) * DD + k4];
        rb[it] = *(const uint2*)&Bm[(size_t)(n0 + m) * DD + k4];
    }
#pragma unroll
    for (int it = 0; it < 4; it++) {
        int m = it * 32 + mld;
        *(uint2*)&As[0][m * LDA + k4] = ra[it];
        *(uint2*)&Bs[0][m * LDA + k4] = rb[it];
    }
    __syncthreads();

    for (int kt = 0; kt < 8; kt++) {
        int cur = kt & 1;
        if (kt < 7) {
            int k0 = (kt + 1) * 32;
#pragma unroll
            for (int it = 0; it < 4; it++) {
                int m = it * 32 + mld;
                ra[it] = *(const uint2*)&A[(size_t)(m0 + m) * DD + k0 + k4];
                rb[it] = *(const uint2*)&Bm[(size_t)(n0 + m) * DD + k0 + k4];
            }
        }
        warp_mma<0,0,LDA,LDA>(As[cur], Bs[cur], acc, lane, wm, wn, 0);
        warp_mma<0,0,LDA,LDA>(As[cur], Bs[cur], acc, lane, wm, wn, 16);
        if (kt < 7) {
#pragma unroll
            for (int it = 0; it < 4; it++) {
                int m = it * 32 + mld;
                *(uint2*)&As[cur ^ 1][m * LDA + k4] = ra[it];
                *(uint2*)&Bs[cur ^ 1][m * LDA + k4] = rb[it];
            }
        }
        __syncthreads();
    }

    // epilogue: relu/scale, store S, register-accumulated row/col sums
    float racc[4] = {0.f, 0.f, 0.f, 0.f};
#pragma unroll
    for (int j = 0; j < 8; j++) {
        int cl = wn + j * 8 + 2 * (lane & 3);
        float c0 = 0.f, c1 = 0.f;
#pragma unroll
        for (int i = 0; i < 2; i++) {
            int rl = wm + i * 16 + (lane >> 2);
            float* d = acc[i][j];
            float v0 = fmaxf(d[0] * 0.0625f, 0.f);
            float v1 = fmaxf(d[1] * 0.0625f, 0.f);
            float v2 = fmaxf(d[2] * 0.0625f, 0.f);
            float v3 = fmaxf(d[3] * 0.0625f, 0.f);
            *(__half2*)&C[(size_t)(m0 + rl) * TT + n0 + cl]     = __floats2half2_rn(v0, v1);
            *(__half2*)&C[(size_t)(m0 + rl + 8) * TT + n0 + cl] = __floats2half2_rn(v2, v3);
            racc[i*2]     += v0 + v1;
            racc[i*2 + 1] += v2 + v3;
            c0 += v0 + v2;
            c1 += v1 + v3;
        }
        atomicAdd(&scol_s[cl],     c0);
        atomicAdd(&scol_s[cl + 1], c1);
    }
#pragma unroll
    for (int q = 0; q < 4; q++)
        atomicAdd(&srow_s[wm + (q >> 1) * 16 + (q & 1) * 8 + (lane >> 2)], racc[q]);
    __syncthreads();
    if (t < 128) {
        atomicAdd(&g_srow[b * TT + m0 + t], srow_s[t]);
        atomicAdd(&g_scol[b * TT + n0 + t], scol_s[t]);
    }
}

// mask 8 halfs (uint4) against threshold tr (fp32 compare), accumulate into accm
__device__ __forceinline__ uint4 mask8(uint4 x, float tr, float& accm) {
    __half2* h = (__half2*)&x;
    uint4 r;
    __half2* o = (__half2*)&r;
#pragma unroll
    for (int i = 0; i < 4; i++) {
        float2 f = __half22float2(h[i]);
        float a0 = f.x > tr ? f.x : 0.f;
        float a1 = f.y > tr ? f.y : 0.f;
        accm += a0 + a1;
        o[i] = __floats2half2_rn(a0, a1);
    }
    return r;
}

// SMEM sizing for the merged agg kernel: A double-buffered (register-staged),
// B 3-stage cp.async.
#define AGGV_AS   (128 * LDA)                 // 5120 halfs per buffer
#define AGGV_BS   (32 * LDB2)                 // 8448 halfs per buffer
#define AGGA_AS   (32 * LDT)                  // 4352 halfs per buffer
#define AGG_SMEM  ((2*AGGV_AS + 3*AGGV_BS) * 2 + 3 * 128 * 4)   // v-role is larger

// ---------------- v-role body: v_out = v_f + (masked S) @ Ab2 * rcp_row ------
__device__ __forceinline__ void agg_v_body(char* smraw, const float* __restrict__ v_f,
                                           const float* __restrict__ thr_p) {
    __half* As   = (__half*)smraw;                        // [2][128*LDA]
    __half* Bst  = As + 2 * AGGV_AS;                      // [3][32*LDB2]
    float*  trs  = (float*)(Bst + 3 * AGGV_BS);           // [128]
    float*  ses  = trs + 128;
    float*  msum = ses + 128;
    int b = blockIdx.y, m0 = blockIdx.x * 128;
    int t = threadIdx.x, lane = t & 31, w = t >> 5;
    int wm = (w & 3) * 32, wn = (w >> 2) * 64;
    if (t < 128) {
        float s = g_srow[b * TT + m0 + t] + EPS_SUM;
        ses[t] = s;
        trs[t] = thr_p[0] * s;
        msum[t] = 0.f;
    }
    const __half* Sb = g_S + (size_t)b * TT * TT;
    const __half* Bg = g_ab2 + (size_t)b * TT * DD;
    float acc[2][8][4] = {};
    float macc = 0.f;
    int srow0 = t >> 2, sseg = (t & 3) * 8;
    int bq = t >> 5, bn8 = (t & 31) * 8;
    uint4 xs;

    auto issueB = [&](int st, int k0) {
        uint32_t b0 = sm_u32(Bst + st * AGGV_BS);
        cpa16(b0 + (bq * LDB2 + bn8) * 2,        &Bg[(size_t)(k0 + bq) * DD + bn8]);
        cpa16(b0 + ((bq + 16) * LDB2 + bn8) * 2, &Bg[(size_t)(k0 + bq + 16) * DD + bn8]);
        cpa_commit();
    };
    issueB(0, 0);
    issueB(1, 32);
    __syncthreads();   // trs ready before mask8
    xs = *(const uint4*)&Sb[(size_t)(m0 + srow0) * TT + sseg];
    *(uint4*)&As[srow0 * LDA + sseg] = mask8(xs, trs[srow0], macc);

    for (int kt = 0; kt < 64; kt++) {
        if (kt == 63) cpa_wait<0>(); else cpa_wait<1>();
        __syncthreads();
        int cur = kt & 1;
        if (kt < 63) {
            int k0 = (kt + 1) * 32;
            xs = *(const uint4*)&Sb[(size_t)(m0 + srow0) * TT + k0 + sseg];
        }
        const __half* Ac = As + cur * AGGV_AS;
        const __half* Bc = Bst + (kt % 3) * AGGV_BS;
        warp_mma<0,1,LDA,LDB2>(Ac, Bc, acc, lane, wm, wn, 0);
        warp_mma<0,1,LDA,LDB2>(Ac, Bc, acc, lane, wm, wn, 16);
        if (kt < 63) {
            __half* An = As + (cur ^ 1) * AGGV_AS;
            *(uint4*)&An[srow0 * LDA + sseg] = mask8(xs, trs[srow0], macc);
            issueB((kt + 2) % 3, (kt + 2) * 32);
        }
    }
    __syncthreads();
    atomicAdd(&msum[srow0], macc);
    __syncthreads();
#pragma unroll
    for (int i = 0; i < 2; i++) {
        int rl = wm + i * 16 + (lane >> 2);
        int row0 = b * TT + m0 + rl;
        int row8 = row0 + 8;
        float rcp0 = 1.f / (msum[rl]     + EPS_SUM * ses[rl]);
        float rcp8 = 1.f / (msum[rl + 8] + EPS_SUM * ses[rl + 8]);
#pragma unroll
        for (int j = 0; j < 8; j++) {
            int c = wn + j * 8 + 2 * (lane & 3);
            float* d = acc[i][j];
            size_t o0 = (size_t)row0 * DD + c;
            size_t o8 = (size_t)row8 * DD + c;
            *(__half2*)&g_vout[o0] =
                __floats2half2_rn(v_f[o0] + d[0] * rcp0, v_f[o0 + 1] + d[1] * rcp0);
            *(__half2*)&g_vout[o8] =
                __floats2half2_rn(v_f[o8] + d[2] * rcp8, v_f[o8 + 1] + d[3] * rcp8);
        }
    }
}

// ---------------- a-role body: a_out = a_f + (masked S)^T @ Vb1 * rcp_col ----
__device__ __forceinline__ void agg_a_body(char* smraw, const float* __restrict__ a_f,
                                           const float* __restrict__ thr_p) {
    __half* Ast  = (__half*)smraw;                        // [2][32*LDT]
    __half* Bst  = Ast + 2 * AGGA_AS;                     // [3][32*LDB2]
    float*  tcs  = (float*)(Bst + 3 * AGGV_BS);           // [128]
    float*  ces  = tcs + 128;
    float*  msum = ces + 128;
    int b = blockIdx.y, m0 = blockIdx.x * 128;
    int t = threadIdx.x, lane = t & 31, w = t >> 5;
    int wm = (w & 3) * 32, wn = (w >> 2) * 64;
    if (t < 128) {
        float s = g_scol[b * TT + m0 + t] + EPS_SUM;
        ces[t] = s;
        tcs[t] = thr_p[0] * s;
        msum[t] = 0.f;
    }
    const __half* Sb = g_S + (size_t)b * TT * TT;
    const __half* Bg = g_vb1 + (size_t)b * TT * DD;
    float acc[2][8][4] = {};
    float cacc[8] = {};
    int sk0 = t >> 4, m8 = (t & 15) * 8;
    int bq = t >> 5, bn8 = (t & 31) * 8;
    uint4 xs;

    auto maskc = [&](uint4 x) {
        __half2* h = (__half2*)&x;
        uint4 r;
        __half2* o = (__half2*)&r;
#pragma unroll
        for (int i = 0; i < 4; i++) {
            float2 f = __half22float2(h[i]);
            float a0 = f.x > tcs[m8 + 2*i]     ? f.x : 0.f;
            float a1 = f.y > tcs[m8 + 2*i + 1] ? f.y : 0.f;
            cacc[2*i]     += a0;
            cacc[2*i + 1] += a1;
            o[i] = __floats2half2_rn(a0, a1);
        }
        return r;
    };

    auto issueB = [&](int st, int k0) {
        uint32_t b0 = sm_u32(Bst + st * AGGV_BS);
        cpa16(b0 + (bq * LDB2 + bn8) * 2,        &Bg[(size_t)(k0 + bq) * DD + bn8]);
        cpa16(b0 + ((bq + 16) * LDB2 + bn8) * 2, &Bg[(size_t)(k0 + bq + 16) * DD + bn8]);
        cpa_commit();
    };
    issueB(0, 0);
    issueB(1, 32);
    __syncthreads();   // tcs ready before maskc
    xs = *(const uint4*)&Sb[(size_t)sk0 * TT + m0 + m8];
    *(uint4*)&Ast[sk0 * LDT + m8] = maskc(xs);

    for (int kt = 0; kt < 64; kt++) {
        if (kt == 63) cpa_wait<0>(); else cpa_wait<1>();
        __syncthreads();
        int cur = kt & 1;
        if (kt < 63) {
            int k0 = (kt + 1) * 32;
            xs = *(const uint4*)&Sb[(size_t)(k0 + sk0) * TT + m0 + m8];
        }
        const __half* Ac = Ast + cur * AGGA_AS;
        const __half* Bc = Bst + (kt % 3) * AGGV_BS;
        warp_mma<1,1,LDT,LDB2>(Ac, Bc, acc, lane, wm, wn, 0);
        warp_mma<1,1,LDT,LDB2>(Ac, Bc, acc, lane, wm, wn, 16);
        if (kt < 63) {
            __half* An = Ast + (cur ^ 1) * AGGA_AS;
            *(uint4*)&An[sk0 * LDT + m8] = maskc(xs);
            issueB((kt + 2) % 3, (kt + 2) * 32);
        }
    }
    __syncthreads();
#pragma unroll
    for (int q = 0; q < 8; q++)
        atomicAdd(&msum[m8 + q], cacc[q]);
    __syncthreads();
#pragma unroll
    for (int i = 0; i < 2; i++) {
        int rl = wm + i * 16 + (lane >> 2);
        int row0 = b * TT + m0 + rl;
        int row8 = row0 + 8;
        float rcp0 = 1.f / (msum[rl]     + EPS_SUM * ces[rl]);
        float rcp8 = 1.f / (msum[rl + 8] + EPS_SUM * ces[rl + 8]);
#pragma unroll
        for (int j = 0; j < 8; j++) {
            int c = wn + j * 8 + 2 * (lane & 3);
            float* d = acc[i][j];
            size_t o0 = (size_t)row0 * DD + c;
            size_t o8 = (size_t)row8 * DD + c;
            *(__half2*)&g_aout[o0] =
                __floats2half2_rn(a_f[o0] + d[0] * rcp0, a_f[o0 + 1] + d[1] * rcp0);
            *(__half2*)&g_aout[o8] =
                __floats2half2_rn(a_f[o8] + d[2] * rcp8, a_f[o8 + 1] + d[3] * rcp8);
        }
    }
}

// ---------------- merged agg kernel: z=0 -> v role, z=1 -> a role ------------
__global__ __launch_bounds__(512, 1) void k_agg(const float* __restrict__ v_f,
                                                const float* __restrict__ a_f,
                                                const float* __restrict__ thr_p) {
    extern __shared__ char smraw[];
    if (blockIdx.z == 0) agg_v_body(smraw, v_f, thr_p);
    else                 agg_a_body(smraw, a_f, thr_p);
}

// ---------------- K6: fused output GEMMs + relu + layernorm + combine --------
// (reverted to the proven R15 config: 3-stage cp.async + SMEM Vs park tile)
#define LNV 258                                    // Vs row stride (floats, even)
#define OUT_AB (64 * LDA)
#define OUT_BB (256 * LDA)
#define OUT_SMEM (3*OUT_AB*2 + 3*OUT_BB*2 + 64*LNV*4 + (64 + 64 + 256 + 256)*4)
__global__ __launch_bounds__(256) void k_out_ln(const float* __restrict__ lns,
                                                const float* __restrict__ lnb,
                                                float* __restrict__ out) {
    extern __shared__ char smraw[];
    __half* As  = (__half*)smraw;                  // [3][64*LDA]
    __half* Bs  = As + 3 * OUT_AB;                 // [3][256*LDA]
    float* Vs   = (float*)(Bs + 3 * OUT_BB);       // 64*LNV floats
    float* rsum = Vs + 64 * LNV;                   // 64
    float* rsq  = rsum + 64;                       // 64
    float* scs  = rsq + 64;                        // 256
    float* bis  = scs + 256;                       // 256
    int m0 = blockIdx.x * 64;
    int t = threadIdx.x, lane = t & 31, w = t >> 5;
    int wm = (w & 1) * 32, wn = (w >> 1) * 64;
    scs[t] = lns[t];
    bis[t] = lnb[t];
    int ar = t >> 2, sg = (t & 3) * 8;   // A: 1 chunk/thread; B: 4 chunks/thread

    for (int z = 0; z < 2; z++) {
        const __half* X = z ? g_aout : g_vout;
        const __half* Wh = z ? g_wa_h : g_wv_h;
        float acc[2][8][4] = {};

        auto issue = [&](int st, int k0) {
            uint32_t a0 = sm_u32(As + st * OUT_AB);
            uint32_t b0 = sm_u32(Bs + st * OUT_BB);
            cpa16(a0 + (ar * LDA + sg) * 2, &X[(size_t)(m0 + ar) * DD + k0 + sg]);
#pragma unroll
            for (int q = 0; q < 4; q++) {
                int n = q * 64 + ar;
                cpa16(b0 + (n * LDA + sg) * 2, &Wh[(size_t)n * DD + k0 + sg]);
            }
            cpa_commit();
        };
        issue(0, 0);
        issue(1, 32);

        for (int kt = 0; kt < 8; kt++) {
            if (kt == 7) cpa_wait<0>(); else cpa_wait<1>();
            __syncthreads();
            int cur = kt % 3;
            warp_mma<0,0,LDA,LDA>(As + cur * OUT_AB, Bs + cur * OUT_BB, acc, lane, wm, wn, 0);
            warp_mma<0,0,LDA,LDA>(As + cur * OUT_AB, Bs + cur * OUT_BB, acc, lane, wm, wn, 16);
            if (kt + 2 < 8) issue((kt + 2) % 3, (kt + 2) * 32);
            __syncthreads();
        }

        // relu + per-row sum/sumsq partials
        if (t < 64) { rsum[t] = 0.f; rsq[t] = 0.f; }
        __syncthreads();
#pragma unroll
        for (int i = 0; i < 2; i++) {
            float ps0 = 0.f, pq0 = 0.f, ps1 = 0.f, pq1 = 0.f;
#pragma unroll
            for (int j = 0; j < 8; j++) {
                float* d = acc[i][j];
                d[0] = fmaxf(d[0], 0.f); d[1] = fmaxf(d[1], 0.f);
                d[2] = fmaxf(d[2], 0.f); d[3] = fmaxf(d[3], 0.f);
                ps0 += d[0] + d[1]; pq0 += d[0]*d[0] + d[1]*d[1];
                ps1 += d[2] + d[3]; pq1 += d[2]*d[2] + d[3]*d[3];
            }
            int rl = wm + i * 16 + (lane >> 2);
            atomicAdd(&rsum[rl], ps0);     atomicAdd(&rsq[rl], pq0);
            atomicAdd(&rsum[rl + 8], ps1); atomicAdd(&rsq[rl + 8], pq1);
        }
        __syncthreads();

        // layernorm; z=0 parks normalized tile in Vs, z=1 combines for av
        float* dst = out + (size_t)(z + 1) * BT * DD;
#pragma unroll
        for (int i = 0; i < 2; i++) {
#pragma unroll
            for (int h = 0; h < 2; h++) {
                int rl = wm + i * 16 + (lane >> 2) + h * 8;
                float mu = rsum[rl] * (1.f / 256.f);
                float var = rsq[rl] * (1.f / 256.f) - mu * mu;
                float rr = rsqrtf(var + EPS_LN);
                size_t rowoff = (size_t)(m0 + rl) * DD;
#pragma unroll
                for (int j = 0; j < 8; j++) {
                    int c = wn + j * 8 + 2 * (lane & 3);
                    float* d = acc[i][j];
                    float o0 = (d[h*2]     - mu) * rr * scs[c]     + bis[c];
                    float o1 = (d[h*2 + 1] - mu) * rr * scs[c + 1] + bis[c + 1];
                    *(float2*)&dst[rowoff + c] = make_float2(o0, o1);
                    if (z == 0) {
                        *(float2*)&Vs[rl * LNV + c] = make_float2(o0, o1);
                    } else {
                        float2 vv = *(float2*)&Vs[rl * LNV + c];
                        *(float2*)&out[rowoff + c] =
                            make_float2(0.4f * (o0 + vv.x), 0.4f * (o1 + vv.y));
                    }
                }
            }
        }
        __syncthreads();
    }
}

// ---------------- launch -----------------------------------------------------
extern "C" void kernel_launch(void* const* d_in, const int* in_sizes, int n_in,
                              void* d_out, int out_size) {
    const float* a_f  = (const float*)d_in[0];
    const float* v_f  = (const float*)d_in[1];
    const float* thr  = (const float*)d_in[2];
    const float* Wv1  = (const float*)d_in[3];
    const float* Wv2  = (const float*)d_in[4];
    const float* Wvfc = (const float*)d_in[5];
    const float* Wa1  = (const float*)d_in[6];
    const float* Wa2  = (const float*)d_in[7];
    const float* Wac  = (const float*)d_in[8];
    const float* lns  = (const float*)d_in[9];
    const float* lnb  = (const float*)d_in[10];
    float* out = (float*)d_out;

    cudaFuncSetAttribute(k_agg, cudaFuncAttributeMaxDynamicSharedMemorySize, AGG_SMEM);
    cudaFuncSetAttribute(k_out_ln, cudaFuncAttributeMaxDynamicSharedMemorySize, OUT_SMEM);

    k_in_gemm<<<dim3(2, 128, 4), 256>>>(v_f, a_f, Wv1, Wv2, Wa1, Wa2, Wvfc, Wac);
    k_scores<<<dim3(16, 16, 8), 256>>>();
    k_agg<<<dim3(16, 8, 2), 512, AGG_SMEM>>>(v_f, a_f, thr);
    k_out_ln<<<BT/64, 256, OUT_SMEM>>>(lns, lnb, out);
}